// round 3
// baseline (speedup 1.0000x reference)
#include <cuda_runtime.h>

#define DIM 512
#define HEADS 8
#define HEAD_DIM 64
#define BATCH 2
#define SEQ 4096
#define M_TOT (BATCH*SEQ)           // 8192
#define ATTN_SCALE 0.125f           // 64^-0.5

// Scratch (allocation-free: device globals)
__device__ float g_q[BATCH*HEADS*SEQ*HEAD_DIM];
__device__ float g_k[BATCH*HEADS*SEQ*HEAD_DIM];
__device__ float g_v[BATCH*HEADS*SEQ*HEAD_DIM];
__device__ float g_attn[M_TOT*DIM];

// ---------------------------------------------------------------------------
// SGEMM NT mainloop: C[m,n] = sum_k A[m,k] * W[n,k]
// BM=BN=128, BK=16, 256 threads, 8x8 microtile.
// ---------------------------------------------------------------------------

__global__ __launch_bounds__(256) void qkv_gemm(const float* __restrict__ A,
                                                const float* __restrict__ W,
                                                const float* __restrict__ bias) {
    __shared__ float As[16][132];
    __shared__ float Bs[16][132];
    const int m0 = blockIdx.y * 128;
    const int n0 = blockIdx.x * 128;
    const int tid = threadIdx.x;
    const int tm0 = (tid >> 4) * 8;
    const int tn4 = (tid & 15) * 4;

    float acc[8][8];
#pragma unroll
    for (int i = 0; i < 8; i++)
#pragma unroll
        for (int j = 0; j < 8; j++) acc[i][j] = 0.f;

    for (int k0 = 0; k0 < DIM; k0 += 16) {
#pragma unroll
        for (int l = 0; l < 2; l++) {
            int idx = tid + l * 256;          // 0..511
            int row = idx >> 2;
            int kc  = (idx & 3) * 4;
            float4 va = *(const float4*)(A + (size_t)(m0 + row) * DIM + k0 + kc);
            As[kc+0][row] = va.x; As[kc+1][row] = va.y;
            As[kc+2][row] = va.z; As[kc+3][row] = va.w;
            float4 vb = *(const float4*)(W + (size_t)(n0 + row) * DIM + k0 + kc);
            Bs[kc+0][row] = vb.x; Bs[kc+1][row] = vb.y;
            Bs[kc+2][row] = vb.z; Bs[kc+3][row] = vb.w;
        }
        __syncthreads();
#pragma unroll
        for (int k = 0; k < 16; k++) {
            float a[8], b[8];
            *(float4*)(a)     = *(const float4*)&As[k][tm0];
            *(float4*)(a + 4) = *(const float4*)&As[k][tm0 + 4];
            *(float4*)(b)     = *(const float4*)&Bs[k][tn4];
            *(float4*)(b + 4) = *(const float4*)&Bs[k][tn4 + 64];
#pragma unroll
            for (int i = 0; i < 8; i++)
#pragma unroll
                for (int j = 0; j < 8; j++)
                    acc[i][j] += a[i] * b[j];
        }
        __syncthreads();
    }

    // Epilogue: bias add + scatter into q/k/v [b,h,n,d]
#pragma unroll
    for (int i = 0; i < 8; i++) {
        int m  = m0 + tm0 + i;
        int b  = m >> 12;          // /4096
        int nn = m & 4095;
#pragma unroll
        for (int jj = 0; jj < 8; jj++) {
            int n = n0 + tn4 + ((jj < 4) ? jj : (64 + jj - 4));
            float val = acc[i][jj] + bias[n];
            int which = n >> 9;    // 0=q,1=k,2=v
            int cc = n & 511;
            int h  = cc >> 6;
            int d  = cc & 63;
            float* dst = (which == 0) ? g_q : ((which == 1) ? g_k : g_v);
            dst[(((size_t)b * HEADS + h) * SEQ + nn) * HEAD_DIM + d] = val;
        }
    }
}

__global__ __launch_bounds__(256) void proj_gemm(const float* __restrict__ W,
                                                 const float* __restrict__ bias,
                                                 float* __restrict__ out) {
    __shared__ float As[16][132];
    __shared__ float Bs[16][132];
    const int m0 = blockIdx.y * 128;
    const int n0 = blockIdx.x * 128;
    const int tid = threadIdx.x;
    const int tm0 = (tid >> 4) * 8;
    const int tn4 = (tid & 15) * 4;
    const float* A = g_attn;

    float acc[8][8];
#pragma unroll
    for (int i = 0; i < 8; i++)
#pragma unroll
        for (int j = 0; j < 8; j++) acc[i][j] = 0.f;

    for (int k0 = 0; k0 < DIM; k0 += 16) {
#pragma unroll
        for (int l = 0; l < 2; l++) {
            int idx = tid + l * 256;
            int row = idx >> 2;
            int kc  = (idx & 3) * 4;
            float4 va = *(const float4*)(A + (size_t)(m0 + row) * DIM + k0 + kc);
            As[kc+0][row] = va.x; As[kc+1][row] = va.y;
            As[kc+2][row] = va.z; As[kc+3][row] = va.w;
            float4 vb = *(const float4*)(W + (size_t)(n0 + row) * DIM + k0 + kc);
            Bs[kc+0][row] = vb.x; Bs[kc+1][row] = vb.y;
            Bs[kc+2][row] = vb.z; Bs[kc+3][row] = vb.w;
        }
        __syncthreads();
#pragma unroll
        for (int k = 0; k < 16; k++) {
            float a[8], b[8];
            *(float4*)(a)     = *(const float4*)&As[k][tm0];
            *(float4*)(a + 4) = *(const float4*)&As[k][tm0 + 4];
            *(float4*)(b)     = *(const float4*)&Bs[k][tn4];
            *(float4*)(b + 4) = *(const float4*)&Bs[k][tn4 + 64];
#pragma unroll
            for (int i = 0; i < 8; i++)
#pragma unroll
                for (int j = 0; j < 8; j++)
                    acc[i][j] += a[i] * b[j];
        }
        __syncthreads();
    }

#pragma unroll
    for (int i = 0; i < 8; i++) {
        int m = m0 + tm0 + i;
#pragma unroll
        for (int jj = 0; jj < 8; jj++) {
            int n = n0 + tn4 + ((jj < 4) ? jj : (64 + jj - 4));
            out[(size_t)m * DIM + n] = acc[i][jj] + bias[n];
        }
    }
}

// ---------------------------------------------------------------------------
// Flash attention. One block = one (b,h) and 64 query rows.
// 256 threads: thread (row = tid>>2, sub = tid&3).
// Q row in registers (pre-scaled). K/V tiles in static smem, pitch 68 floats.
// P exchanged within the 4-lane row group via width-4 shuffles (no smem).
// Static smem total: 2*64*68*4 = 34,816 B (< 48 KB default; no attribute call)
// ---------------------------------------------------------------------------
#define KV_PITCH 68

__global__ __launch_bounds__(256) void flash_attn() {
    __shared__ float k_s[64 * KV_PITCH];
    __shared__ float v_s[64 * KV_PITCH];

    const int bh  = blockIdx.x >> 6;       // 0..15
    const int qt  = blockIdx.x & 63;       // query tile
    const int tid = threadIdx.x;
    const int row = tid >> 2;
    const int sub = tid & 3;

    const float* qptr = g_q + ((size_t)bh * SEQ + qt * 64 + row) * HEAD_DIM;
    float q[64];
#pragma unroll
    for (int i = 0; i < 64; i += 4) {
        float4 t = *(const float4*)(qptr + i);
        q[i+0] = t.x * ATTN_SCALE; q[i+1] = t.y * ATTN_SCALE;
        q[i+2] = t.z * ATTN_SCALE; q[i+3] = t.w * ATTN_SCALE;
    }

    float o[16];
#pragma unroll
    for (int i = 0; i < 16; i++) o[i] = 0.f;
    float m_run = -1e30f, l_run = 0.f;

    const float* kbase = g_k + (size_t)bh * SEQ * HEAD_DIM;
    const float* vbase = g_v + (size_t)bh * SEQ * HEAD_DIM;

    for (int kt = 0; kt < SEQ / 64; kt++) {
        __syncthreads();
#pragma unroll
        for (int l = 0; l < 4; l++) {
            int idx = tid + l * 256;       // 0..1023
            int kc = idx >> 4;
            int d4 = idx & 15;
            float4 kv = *(const float4*)(kbase + ((size_t)kt * 64 + kc) * HEAD_DIM + d4 * 4);
            *(float4*)(k_s + kc * KV_PITCH + d4 * 4) = kv;
            float4 vv = *(const float4*)(vbase + ((size_t)kt * 64 + kc) * HEAD_DIM + d4 * 4);
            *(float4*)(v_s + kc * KV_PITCH + d4 * 4) = vv;
        }
        __syncthreads();

        // S = q . k for this thread's 16 interleaved key columns (kc = 4j+sub)
        float s[16];
#pragma unroll
        for (int j = 0; j < 16; j++) {
            const float* kr = k_s + (j * 4 + sub) * KV_PITCH;
            float acc = 0.f;
#pragma unroll
            for (int d4 = 0; d4 < 16; d4++) {
                float4 kv = *(const float4*)(kr + d4 * 4);
                acc += q[d4*4+0]*kv.x + q[d4*4+1]*kv.y
                     + q[d4*4+2]*kv.z + q[d4*4+3]*kv.w;
            }
            s[j] = acc;
        }

        // online softmax (reduce across the 4 sub-threads of this row)
        float mt = s[0];
#pragma unroll
        for (int j = 1; j < 16; j++) mt = fmaxf(mt, s[j]);
        mt = fmaxf(mt, __shfl_xor_sync(0xffffffffu, mt, 1));
        mt = fmaxf(mt, __shfl_xor_sync(0xffffffffu, mt, 2));
        float m_new = fmaxf(m_run, mt);
        float alpha = __expf(m_run - m_new);
        m_run = m_new;

        float ls = 0.f;
#pragma unroll
        for (int j = 0; j < 16; j++) {
            float p = __expf(s[j] - m_new);
            s[j] = p;                          // s now holds P
            ls += p;
        }
        ls += __shfl_xor_sync(0xffffffffu, ls, 1);
        ls += __shfl_xor_sync(0xffffffffu, ls, 2);
        l_run = l_run * alpha + ls;

#pragma unroll
        for (int i = 0; i < 16; i++) o[i] *= alpha;

        // O += P @ V. p for column kc=4j+ss lives on lane ss (width-4 shfl).
        // This thread owns dims d = (jd*4+sub)*4 .. +3.
#pragma unroll
        for (int j = 0; j < 16; j++) {
#pragma unroll
            for (int ss = 0; ss < 4; ss++) {
                float p = __shfl_sync(0xffffffffu, s[j], ss, 4);
                const float* vr = v_s + (j * 4 + ss) * KV_PITCH;
#pragma unroll
                for (int jd = 0; jd < 4; jd++) {
                    float4 vv = *(const float4*)(vr + (jd * 4 + sub) * 4);
                    o[jd*4+0] += p * vv.x; o[jd*4+1] += p * vv.y;
                    o[jd*4+2] += p * vv.z; o[jd*4+3] += p * vv.w;
                }
            }
        }
    }

    const float inv = 1.f / l_run;
    const int b = bh >> 3, h = bh & 7;
    const int n = qt * 64 + row;
    float* obase = g_attn + (((size_t)b * SEQ + n) * HEADS + h) * HEAD_DIM;
#pragma unroll
    for (int jd = 0; jd < 4; jd++) {
        float4 ov;
        ov.x = o[jd*4+0] * inv; ov.y = o[jd*4+1] * inv;
        ov.z = o[jd*4+2] * inv; ov.w = o[jd*4+3] * inv;
        *(float4*)(obase + (jd * 4 + sub) * 4) = ov;
    }
}

// ---------------------------------------------------------------------------

extern "C" void kernel_launch(void* const* d_in, const int* in_sizes, int n_in,
                              void* d_out, int out_size) {
    const float* x      = (const float*)d_in[0];
    const float* qkv_w  = (const float*)d_in[1];
    const float* qkv_b  = (const float*)d_in[2];
    const float* proj_w = (const float*)d_in[3];
    const float* proj_b = (const float*)d_in[4];
    float* out = (float*)d_out;

    qkv_gemm<<<dim3(12, 64), 256>>>(x, qkv_w, qkv_b);     // [8192,512]x[512,1536]
    flash_attn<<<16 * (SEQ / 64), 256>>>();               // 1024 blocks
    proj_gemm<<<dim3(4, 64), 256>>>(proj_w, proj_b, out); // [8192,512]x[512,512]
}

// round 5
// speedup vs baseline: 4.2747x; 4.2747x over previous
#include <cuda_runtime.h>
#include <cstdint>

#define DIM 512
#define HEADS 8
#define HEAD_DIM 64
#define BATCH 2
#define SEQ 4096
#define M_TOT (BATCH*SEQ)           // 8192
#define ATTN_SCALE 0.125f           // 64^-0.5

// Scratch (allocation-free: device globals)
__device__ float g_q[BATCH*HEADS*SEQ*HEAD_DIM];
__device__ float g_k[BATCH*HEADS*SEQ*HEAD_DIM];
__device__ float g_v[BATCH*HEADS*SEQ*HEAD_DIM];
__device__ float g_attn[M_TOT*DIM];

// ---------------------------------------------------------------------------
// mma.sync m16n8k8 tf32 (baseline PTX, works on .target sm_103)
// ---------------------------------------------------------------------------
__device__ __forceinline__ void mma_tf32(float* d, const uint32_t* a,
                                         uint32_t b0, uint32_t b1) {
    asm volatile(
        "mma.sync.aligned.m16n8k8.row.col.f32.tf32.tf32.f32 "
        "{%0,%1,%2,%3}, {%4,%5,%6,%7}, {%8,%9}, {%0,%1,%2,%3};"
        : "+f"(d[0]), "+f"(d[1]), "+f"(d[2]), "+f"(d[3])
        : "r"(a[0]), "r"(a[1]), "r"(a[2]), "r"(a[3]), "r"(b0), "r"(b1));
}

__device__ __forceinline__ uint32_t f2tf32(float x) {
    uint32_t r;
    asm("cvt.rna.tf32.f32 %0, %1;" : "=r"(r) : "f"(x));
    return r;
}

// ---------------------------------------------------------------------------
// Flash attention, tensor-core path.
// CTA: 256 threads (8 warps), 128 query rows (warp w owns rows w*16..w*16+15).
// K/V tiles (128 x 64) staged in smem, pitch 72 floats.
// ---------------------------------------------------------------------------
#define PITCH 72
#define TILE_U32 (128 * PITCH)                 // per-buffer u32 count
#define FLASH_DYN (2 * TILE_U32 * 4)           // 73,728 B

__global__ __launch_bounds__(256, 1) void flash_attn_mma() {
    extern __shared__ uint32_t sbuf[];
    uint32_t* bufK = sbuf;                     // also used to stage Q first
    uint32_t* bufV = sbuf + TILE_U32;

    const int tid  = threadIdx.x;
    const int wid  = tid >> 5;
    const int lane = tid & 31;
    const int qp   = lane >> 2;                // quad index = row-within-16 (0..7)
    const int c    = lane & 3;                 // quad position = column pair

    const int bh = blockIdx.x >> 5;
    const int qt = blockIdx.x & 31;

    const float* qbase = g_q + ((size_t)bh * SEQ + (size_t)qt * 128) * HEAD_DIM;
    const float* kbase = g_k + (size_t)bh * SEQ * HEAD_DIM;
    const float* vbase = g_v + (size_t)bh * SEQ * HEAD_DIM;

    // ---- Stage Q (scaled, tf32-rounded) into bufK ----
#pragma unroll
    for (int i = 0; i < 8; i++) {
        int idx = tid + i * 256;               // 0..2047
        int row = idx >> 4, c4 = (idx & 15) * 4;
        float4 v = *(const float4*)(qbase + (size_t)row * HEAD_DIM + c4);
        uint4 u;
        u.x = f2tf32(v.x * ATTN_SCALE); u.y = f2tf32(v.y * ATTN_SCALE);
        u.z = f2tf32(v.z * ATTN_SCALE); u.w = f2tf32(v.w * ATTN_SCALE);
        *(uint4*)(bufK + row * PITCH + c4) = u;
    }
    __syncthreads();

    // ---- Preload Q A-fragments: 8 k-steps x 4 regs ----
    uint32_t qa[32];
#pragma unroll
    for (int ks = 0; ks < 8; ks++) {
        const uint32_t* qlo = bufK + (wid * 16 + qp) * PITCH + ks * 8 + c;
        const uint32_t* qhi = qlo + 8 * PITCH;
        qa[ks*4+0] = qlo[0];
        qa[ks*4+1] = qhi[0];
        qa[ks*4+2] = qlo[4];
        qa[ks*4+3] = qhi[4];
    }
    __syncthreads();

    float oc[8][4];
#pragma unroll
    for (int t = 0; t < 8; t++)
#pragma unroll
        for (int r = 0; r < 4; r++) oc[t][r] = 0.f;
    float m_lo = -1e30f, m_hi = -1e30f;
    float l_lo = 0.f,    l_hi = 0.f;

    for (int kt = 0; kt < SEQ / 128; kt++) {
        // ---- Stage K, V ----
#pragma unroll
        for (int i = 0; i < 8; i++) {
            int idx = tid + i * 256;
            int row = idx >> 4, c4 = (idx & 15) * 4;
            float4 v = *(const float4*)(kbase + ((size_t)kt * 128 + row) * HEAD_DIM + c4);
            uint4 u;
            u.x = f2tf32(v.x); u.y = f2tf32(v.y); u.z = f2tf32(v.z); u.w = f2tf32(v.w);
            *(uint4*)(bufK + row * PITCH + c4) = u;
        }
#pragma unroll
        for (int i = 0; i < 8; i++) {
            int idx = tid + i * 256;
            int row = idx >> 4, c4 = (idx & 15) * 4;
            float4 v = *(const float4*)(vbase + ((size_t)kt * 128 + row) * HEAD_DIM + c4);
            uint4 u;
            u.x = f2tf32(v.x); u.y = f2tf32(v.y); u.z = f2tf32(v.z); u.w = f2tf32(v.w);
            *(uint4*)(bufV + row * PITCH + c4) = u;
        }
        __syncthreads();

        // ---- S = Q @ K^T : 16 n-tiles (8 keys each) x 8 k-steps ----
        float sc[16][4];
#pragma unroll
        for (int t = 0; t < 16; t++)
#pragma unroll
            for (int r = 0; r < 4; r++) sc[t][r] = 0.f;

#pragma unroll
        for (int nt = 0; nt < 16; nt++) {
            const uint32_t* kr = bufK + (nt * 8 + qp) * PITCH + c;
#pragma unroll
            for (int ks = 0; ks < 8; ks++) {
                uint32_t b0 = kr[ks * 8];
                uint32_t b1 = kr[ks * 8 + 4];
                mma_tf32(sc[nt], qa + ks * 4, b0, b1);
            }
        }

        // ---- Online softmax (rows lo = w*16+qp, hi = +8; quad = full row) ----
        float mx_lo = -1e30f, mx_hi = -1e30f;
#pragma unroll
        for (int t = 0; t < 16; t++) {
            mx_lo = fmaxf(mx_lo, fmaxf(sc[t][0], sc[t][1]));
            mx_hi = fmaxf(mx_hi, fmaxf(sc[t][2], sc[t][3]));
        }
        mx_lo = fmaxf(mx_lo, __shfl_xor_sync(0xffffffffu, mx_lo, 1));
        mx_lo = fmaxf(mx_lo, __shfl_xor_sync(0xffffffffu, mx_lo, 2));
        mx_hi = fmaxf(mx_hi, __shfl_xor_sync(0xffffffffu, mx_hi, 1));
        mx_hi = fmaxf(mx_hi, __shfl_xor_sync(0xffffffffu, mx_hi, 2));

        float mn_lo = fmaxf(m_lo, mx_lo);
        float mn_hi = fmaxf(m_hi, mx_hi);
        float al_lo = __expf(m_lo - mn_lo);
        float al_hi = __expf(m_hi - mn_hi);
        m_lo = mn_lo; m_hi = mn_hi;

        float s_lo = 0.f, s_hi = 0.f;
#pragma unroll
        for (int t = 0; t < 16; t++) {
            sc[t][0] = __expf(sc[t][0] - mn_lo);
            sc[t][1] = __expf(sc[t][1] - mn_lo);
            sc[t][2] = __expf(sc[t][2] - mn_hi);
            sc[t][3] = __expf(sc[t][3] - mn_hi);
            s_lo += sc[t][0] + sc[t][1];
            s_hi += sc[t][2] + sc[t][3];
        }
        l_lo = al_lo * l_lo + s_lo;            // per-lane partial; reduced at end
        l_hi = al_hi * l_hi + s_hi;

#pragma unroll
        for (int t = 0; t < 8; t++) {
            oc[t][0] *= al_lo; oc[t][1] *= al_lo;
            oc[t][2] *= al_hi; oc[t][3] *= al_hi;
        }

        // ---- O += P @ V : k-step ks = key octet (= S n-tile ks) ----
#pragma unroll
        for (int ks = 0; ks < 16; ks++) {
            // A-frag from P C-frag via width-4 shuffles
            int s0 = c >> 1;            // source quad-pos for cols 0..3
            int s1 = 2 + (c >> 1);      // source quad-pos for cols 4..7
            float t0 = __shfl_sync(0xffffffffu, sc[ks][0], s0, 4);
            float t1 = __shfl_sync(0xffffffffu, sc[ks][1], s0, 4);
            float t2 = __shfl_sync(0xffffffffu, sc[ks][2], s0, 4);
            float t3 = __shfl_sync(0xffffffffu, sc[ks][3], s0, 4);
            float u0 = __shfl_sync(0xffffffffu, sc[ks][0], s1, 4);
            float u1 = __shfl_sync(0xffffffffu, sc[ks][1], s1, 4);
            float u2 = __shfl_sync(0xffffffffu, sc[ks][2], s1, 4);
            float u3 = __shfl_sync(0xffffffffu, sc[ks][3], s1, 4);
            uint32_t a[4];
            a[0] = __float_as_uint((c & 1) ? t1 : t0);
            a[1] = __float_as_uint((c & 1) ? t3 : t2);
            a[2] = __float_as_uint((c & 1) ? u1 : u0);
            a[3] = __float_as_uint((c & 1) ? u3 : u2);

            const uint32_t* vr = bufV + (ks * 8 + c) * PITCH + qp;
#pragma unroll
            for (int nt = 0; nt < 8; nt++) {
                uint32_t b0 = vr[nt * 8];
                uint32_t b1 = vr[4 * PITCH + nt * 8];
                mma_tf32(oc[nt], a, b0, b1);
            }
        }
        __syncthreads();
    }

    // ---- Final: reduce l across quad, normalize, write ----
    l_lo += __shfl_xor_sync(0xffffffffu, l_lo, 1);
    l_lo += __shfl_xor_sync(0xffffffffu, l_lo, 2);
    l_hi += __shfl_xor_sync(0xffffffffu, l_hi, 1);
    l_hi += __shfl_xor_sync(0xffffffffu, l_hi, 2);
    const float inv_lo = 1.f / l_lo;
    const float inv_hi = 1.f / l_hi;

    const int b = bh >> 3, h = bh & 7;
    const int n_lo = qt * 128 + wid * 16 + qp;
    const int n_hi = n_lo + 8;
    float* olo = g_attn + (((size_t)b * SEQ + n_lo) * HEADS + h) * HEAD_DIM;
    float* ohi = g_attn + (((size_t)b * SEQ + n_hi) * HEADS + h) * HEAD_DIM;
#pragma unroll
    for (int t = 0; t < 8; t++) {
        int d = t * 8 + c * 2;
        *(float2*)(olo + d) = make_float2(oc[t][0] * inv_lo, oc[t][1] * inv_lo);
        *(float2*)(ohi + d) = make_float2(oc[t][2] * inv_hi, oc[t][3] * inv_hi);
    }
}

// ===========================================================================
// Scalar SGEMMs (as in the 4865us baseline; V stored row-major again)
// ===========================================================================
__global__ __launch_bounds__(256) void qkv_gemm(const float* __restrict__ A,
                                                const float* __restrict__ W,
                                                const float* __restrict__ bias) {
    __shared__ float As[16][132];
    __shared__ float Bs[16][132];
    const int m0 = blockIdx.y * 128;
    const int n0 = blockIdx.x * 128;
    const int tid = threadIdx.x;
    const int tm0 = (tid >> 4) * 8;
    const int tn4 = (tid & 15) * 4;

    float acc[8][8];
#pragma unroll
    for (int i = 0; i < 8; i++)
#pragma unroll
        for (int j = 0; j < 8; j++) acc[i][j] = 0.f;

    for (int k0 = 0; k0 < DIM; k0 += 16) {
#pragma unroll
        for (int l = 0; l < 2; l++) {
            int idx = tid + l * 256;
            int row = idx >> 2;
            int kc  = (idx & 3) * 4;
            float4 va = *(const float4*)(A + (size_t)(m0 + row) * DIM + k0 + kc);
            As[kc+0][row] = va.x; As[kc+1][row] = va.y;
            As[kc+2][row] = va.z; As[kc+3][row] = va.w;
            float4 vb = *(const float4*)(W + (size_t)(n0 + row) * DIM + k0 + kc);
            Bs[kc+0][row] = vb.x; Bs[kc+1][row] = vb.y;
            Bs[kc+2][row] = vb.z; Bs[kc+3][row] = vb.w;
        }
        __syncthreads();
#pragma unroll
        for (int k = 0; k < 16; k++) {
            float a[8], b[8];
            *(float4*)(a)     = *(const float4*)&As[k][tm0];
            *(float4*)(a + 4) = *(const float4*)&As[k][tm0 + 4];
            *(float4*)(b)     = *(const float4*)&Bs[k][tn4];
            *(float4*)(b + 4) = *(const float4*)&Bs[k][tn4 + 64];
#pragma unroll
            for (int i = 0; i < 8; i++)
#pragma unroll
                for (int j = 0; j < 8; j++)
                    acc[i][j] += a[i] * b[j];
        }
        __syncthreads();
    }

#pragma unroll
    for (int i = 0; i < 8; i++) {
        int m  = m0 + tm0 + i;
        int b  = m >> 12;
        int nn = m & 4095;
#pragma unroll
        for (int jj = 0; jj < 8; jj++) {
            int n = n0 + tn4 + ((jj < 4) ? jj : (64 + jj - 4));
            float val = acc[i][jj] + bias[n];
            int which = n >> 9;    // 0=q,1=k,2=v
            int cc = n & 511;
            int h  = cc >> 6;
            int d  = cc & 63;
            int bhh = b * HEADS + h;
            float* dst = (which == 0) ? g_q : ((which == 1) ? g_k : g_v);
            dst[((size_t)bhh * SEQ + nn) * HEAD_DIM + d] = val;
        }
    }
}

__global__ __launch_bounds__(256) void proj_gemm(const float* __restrict__ W,
                                                 const float* __restrict__ bias,
                                                 float* __restrict__ out) {
    __shared__ float As[16][132];
    __shared__ float Bs[16][132];
    const int m0 = blockIdx.y * 128;
    const int n0 = blockIdx.x * 128;
    const int tid = threadIdx.x;
    const int tm0 = (tid >> 4) * 8;
    const int tn4 = (tid & 15) * 4;
    const float* A = g_attn;

    float acc[8][8];
#pragma unroll
    for (int i = 0; i < 8; i++)
#pragma unroll
        for (int j = 0; j < 8; j++) acc[i][j] = 0.f;

    for (int k0 = 0; k0 < DIM; k0 += 16) {
#pragma unroll
        for (int l = 0; l < 2; l++) {
            int idx = tid + l * 256;
            int row = idx >> 2;
            int kc  = (idx & 3) * 4;
            float4 va = *(const float4*)(A + (size_t)(m0 + row) * DIM + k0 + kc);
            As[kc+0][row] = va.x; As[kc+1][row] = va.y;
            As[kc+2][row] = va.z; As[kc+3][row] = va.w;
            float4 vb = *(const float4*)(W + (size_t)(n0 + row) * DIM + k0 + kc);
            Bs[kc+0][row] = vb.x; Bs[kc+1][row] = vb.y;
            Bs[kc+2][row] = vb.z; Bs[kc+3][row] = vb.w;
        }
        __syncthreads();
#pragma unroll
        for (int k = 0; k < 16; k++) {
            float a[8], b[8];
            *(float4*)(a)     = *(const float4*)&As[k][tm0];
            *(float4*)(a + 4) = *(const float4*)&As[k][tm0 + 4];
            *(float4*)(b)     = *(const float4*)&Bs[k][tn4];
            *(float4*)(b + 4) = *(const float4*)&Bs[k][tn4 + 64];
#pragma unroll
            for (int i = 0; i < 8; i++)
#pragma unroll
                for (int j = 0; j < 8; j++)
                    acc[i][j] += a[i] * b[j];
        }
        __syncthreads();
    }

#pragma unroll
    for (int i = 0; i < 8; i++) {
        int m = m0 + tm0 + i;
#pragma unroll
        for (int jj = 0; jj < 8; jj++) {
            int n = n0 + tn4 + ((jj < 4) ? jj : (64 + jj - 4));
            out[(size_t)m * DIM + n] = acc[i][jj] + bias[n];
        }
    }
}

// ---------------------------------------------------------------------------

extern "C" void kernel_launch(void* const* d_in, const int* in_sizes, int n_in,
                              void* d_out, int out_size) {
    const float* x      = (const float*)d_in[0];
    const float* qkv_w  = (const float*)d_in[1];
    const float* qkv_b  = (const float*)d_in[2];
    const float* proj_w = (const float*)d_in[3];
    const float* proj_b = (const float*)d_in[4];
    float* out = (float*)d_out;

    cudaFuncSetAttribute(flash_attn_mma,
                         cudaFuncAttributeMaxDynamicSharedMemorySize, FLASH_DYN);

    qkv_gemm<<<dim3(12, 64), 256>>>(x, qkv_w, qkv_b);
    flash_attn_mma<<<16 * (SEQ / 128), 256, FLASH_DYN>>>();
    proj_gemm<<<dim3(4, 64), 256>>>(proj_w, proj_b, out);
}

// round 6
// speedup vs baseline: 4.7346x; 1.1076x over previous
#include <cuda_runtime.h>
#include <cstdint>

#define DIM 512
#define HEADS 8
#define HEAD_DIM 64
#define BATCH 2
#define SEQ 4096
#define M_TOT (BATCH*SEQ)           // 8192
#define ATTN_SCALE 0.125f           // 64^-0.5

// Scratch (allocation-free: device globals)
__device__ float g_q[BATCH*HEADS*SEQ*HEAD_DIM];
__device__ float g_k[BATCH*HEADS*SEQ*HEAD_DIM];
__device__ float g_v[BATCH*HEADS*SEQ*HEAD_DIM];
__device__ float g_attn[M_TOT*DIM];

// ---------------------------------------------------------------------------
// mma.sync m16n8k8 tf32 (baseline PTX, works on .target sm_103)
// ---------------------------------------------------------------------------
__device__ __forceinline__ void mma_tf32(float* d, const uint32_t* a,
                                         uint32_t b0, uint32_t b1) {
    asm volatile(
        "mma.sync.aligned.m16n8k8.row.col.f32.tf32.tf32.f32 "
        "{%0,%1,%2,%3}, {%4,%5,%6,%7}, {%8,%9}, {%0,%1,%2,%3};"
        : "+f"(d[0]), "+f"(d[1]), "+f"(d[2]), "+f"(d[3])
        : "r"(a[0]), "r"(a[1]), "r"(a[2]), "r"(a[3]), "r"(b0), "r"(b1));
}

__device__ __forceinline__ uint32_t f2tf32(float x) {
    uint32_t r;
    asm("cvt.rna.tf32.f32 %0, %1;" : "=r"(r) : "f"(x));
    return r;
}

// ===========================================================================
// Split-precision tf32 tensor-core NT GEMM: C[m,n] = sum_k A[m,k] * W[n,k]
// CTA 128x128, BK=16, 256 threads (8 warps as 2m x 4n, warp tile 64x32).
// Double-buffered smem, register prefetch, one sync per stage.
// x = hi + lo (both tf32); C += ahi*bhi + ahi*blo + alo*bhi  (~fp32 accuracy)
// ===========================================================================
#define GP 20                       // smem pitch (floats), conflict-free frags
#define GSTAGE (128 * GP)

// Computes the 128x128 tile accumulators; caller provides epilogue.
#define GEMM_BODY(Aptr, Wptr)                                                \
    __shared__ float As[2][GSTAGE];                                          \
    __shared__ float Ws[2][GSTAGE];                                          \
    const int tid  = threadIdx.x;                                            \
    const int m0   = blockIdx.y * 128;                                       \
    const int n0   = blockIdx.x * 128;                                       \
    const int wid  = tid >> 5, lane = tid & 31;                              \
    const int qp   = lane >> 2, c = lane & 3;                                \
    const int wm   = (wid >> 2) * 64;                                        \
    const int wn   = (wid & 3) * 32;                                         \
    float C[16][4];                                                          \
    _Pragma("unroll")                                                        \
    for (int t = 0; t < 16; t++)                                             \
        { C[t][0] = 0.f; C[t][1] = 0.f; C[t][2] = 0.f; C[t][3] = 0.f; }      \
    const int srow0 = tid >> 2, sc4 = (tid & 3) * 4;                         \
    const int srow1 = (tid + 256) >> 2;                                      \
    /* stage k0 = 0 into buffer 0 */                                         \
    {                                                                        \
        float4 a0 = *(const float4*)(Aptr + (size_t)(m0 + srow0) * DIM + sc4); \
        float4 a1 = *(const float4*)(Aptr + (size_t)(m0 + srow1) * DIM + sc4); \
        float4 w0 = *(const float4*)(Wptr + (size_t)(n0 + srow0) * DIM + sc4); \
        float4 w1 = *(const float4*)(Wptr + (size_t)(n0 + srow1) * DIM + sc4); \
        *(float4*)(As[0] + srow0 * GP + sc4) = a0;                           \
        *(float4*)(As[0] + srow1 * GP + sc4) = a1;                           \
        *(float4*)(Ws[0] + srow0 * GP + sc4) = w0;                           \
        *(float4*)(Ws[0] + srow1 * GP + sc4) = w1;                           \
    }                                                                        \
    __syncthreads();                                                         \
    for (int s = 0; s < DIM / 16; s++) {                                     \
        const int cur = s & 1;                                               \
        float4 pa0, pa1, pw0, pw1;                                           \
        if (s < DIM / 16 - 1) {                                              \
            int nk = (s + 1) * 16;                                           \
            pa0 = *(const float4*)(Aptr + (size_t)(m0 + srow0) * DIM + nk + sc4); \
            pa1 = *(const float4*)(Aptr + (size_t)(m0 + srow1) * DIM + nk + sc4); \
            pw0 = *(const float4*)(Wptr + (size_t)(n0 + srow0) * DIM + nk + sc4); \
            pw1 = *(const float4*)(Wptr + (size_t)(n0 + srow1) * DIM + nk + sc4); \
        }                                                                    \
        _Pragma("unroll")                                                    \
        for (int kk = 0; kk < 2; kk++) {                                     \
            uint32_t ahi[16], alo[16], bhi[8], blo[8];                       \
            _Pragma("unroll")                                                \
            for (int mt = 0; mt < 4; mt++) {                                 \
                const float* p = As[cur] + (wm + mt * 16 + qp) * GP + kk * 8 + c; \
                float x0 = p[0], x1 = p[8 * GP], x2 = p[4], x3 = p[8 * GP + 4]; \
                ahi[mt*4+0] = f2tf32(x0);                                    \
                ahi[mt*4+1] = f2tf32(x1);                                    \
                ahi[mt*4+2] = f2tf32(x2);                                    \
                ahi[mt*4+3] = f2tf32(x3);                                    \
                alo[mt*4+0] = f2tf32(x0 - __uint_as_float(ahi[mt*4+0]));     \
                alo[mt*4+1] = f2tf32(x1 - __uint_as_float(ahi[mt*4+1]));     \
                alo[mt*4+2] = f2tf32(x2 - __uint_as_float(ahi[mt*4+2]));     \
                alo[mt*4+3] = f2tf32(x3 - __uint_as_float(ahi[mt*4+3]));     \
            }                                                                \
            _Pragma("unroll")                                                \
            for (int nt = 0; nt < 4; nt++) {                                 \
                const float* p = Ws[cur] + (wn + nt * 8 + qp) * GP + kk * 8 + c; \
                float y0 = p[0], y1 = p[4];                                  \
                bhi[nt*2+0] = f2tf32(y0);                                    \
                bhi[nt*2+1] = f2tf32(y1);                                    \
                blo[nt*2+0] = f2tf32(y0 - __uint_as_float(bhi[nt*2+0]));     \
                blo[nt*2+1] = f2tf32(y1 - __uint_as_float(bhi[nt*2+1]));     \
            }                                                                \
            _Pragma("unroll")                                                \
            for (int mt = 0; mt < 4; mt++)                                   \
                _Pragma("unroll")                                            \
                for (int nt = 0; nt < 4; nt++) {                             \
                    mma_tf32(C[mt*4+nt], ahi + mt*4, bhi[nt*2], bhi[nt*2+1]); \
                    mma_tf32(C[mt*4+nt], ahi + mt*4, blo[nt*2], blo[nt*2+1]); \
                    mma_tf32(C[mt*4+nt], alo + mt*4, bhi[nt*2], bhi[nt*2+1]); \
                }                                                            \
        }                                                                    \
        if (s < DIM / 16 - 1) {                                              \
            const int nb = cur ^ 1;                                          \
            *(float4*)(As[nb] + srow0 * GP + sc4) = pa0;                     \
            *(float4*)(As[nb] + srow1 * GP + sc4) = pa1;                     \
            *(float4*)(Ws[nb] + srow0 * GP + sc4) = pw0;                     \
            *(float4*)(Ws[nb] + srow1 * GP + sc4) = pw1;                     \
        }                                                                    \
        __syncthreads();                                                     \
    }

__global__ __launch_bounds__(256) void qkv_gemm_tc(const float* __restrict__ A,
                                                   const float* __restrict__ W,
                                                   const float* __restrict__ bias) {
    GEMM_BODY(A, W)
    // Epilogue: bias add + scatter into q/k/v [bh][n][d]
#pragma unroll
    for (int mt = 0; mt < 4; mt++) {
#pragma unroll
        for (int nt = 0; nt < 4; nt++) {
#pragma unroll
            for (int half = 0; half < 2; half++) {
                int m  = m0 + wm + mt * 16 + qp + half * 8;
                int b  = m >> 12;
                int nn = m & 4095;
                int n  = n0 + wn + nt * 8 + c * 2;
                float v0 = C[mt*4+nt][half*2+0] + bias[n];
                float v1 = C[mt*4+nt][half*2+1] + bias[n + 1];
                int which = n >> 9;
                int cc = n & 511;
                int h  = cc >> 6;
                int d  = cc & 63;
                int bhh = b * HEADS + h;
                float* dst = (which == 0) ? g_q : ((which == 1) ? g_k : g_v);
                *(float2*)(dst + ((size_t)bhh * SEQ + nn) * HEAD_DIM + d) =
                    make_float2(v0, v1);
            }
        }
    }
}

__global__ __launch_bounds__(256) void proj_gemm_tc(const float* __restrict__ W,
                                                    const float* __restrict__ bias,
                                                    float* __restrict__ out) {
    const float* Ain = g_attn;
    GEMM_BODY(Ain, W)
#pragma unroll
    for (int mt = 0; mt < 4; mt++) {
#pragma unroll
        for (int nt = 0; nt < 4; nt++) {
#pragma unroll
            for (int half = 0; half < 2; half++) {
                int m = m0 + wm + mt * 16 + qp + half * 8;
                int n = n0 + wn + nt * 8 + c * 2;
                float v0 = C[mt*4+nt][half*2+0] + bias[n];
                float v1 = C[mt*4+nt][half*2+1] + bias[n + 1];
                *(float2*)(out + (size_t)m * DIM + n) = make_float2(v0, v1);
            }
        }
    }
}

// ---------------------------------------------------------------------------
// Flash attention, tensor-core path (UNCHANGED from the 1138us version).
// ---------------------------------------------------------------------------
#define PITCH 72
#define TILE_U32 (128 * PITCH)
#define FLASH_DYN (2 * TILE_U32 * 4)           // 73,728 B

__global__ __launch_bounds__(256, 1) void flash_attn_mma() {
    extern __shared__ uint32_t sbuf[];
    uint32_t* bufK = sbuf;
    uint32_t* bufV = sbuf + TILE_U32;

    const int tid  = threadIdx.x;
    const int wid  = tid >> 5;
    const int lane = tid & 31;
    const int qp   = lane >> 2;
    const int c    = lane & 3;

    const int bh = blockIdx.x >> 5;
    const int qt = blockIdx.x & 31;

    const float* qbase = g_q + ((size_t)bh * SEQ + (size_t)qt * 128) * HEAD_DIM;
    const float* kbase = g_k + (size_t)bh * SEQ * HEAD_DIM;
    const float* vbase = g_v + (size_t)bh * SEQ * HEAD_DIM;

#pragma unroll
    for (int i = 0; i < 8; i++) {
        int idx = tid + i * 256;
        int row = idx >> 4, c4 = (idx & 15) * 4;
        float4 v = *(const float4*)(qbase + (size_t)row * HEAD_DIM + c4);
        uint4 u;
        u.x = f2tf32(v.x * ATTN_SCALE); u.y = f2tf32(v.y * ATTN_SCALE);
        u.z = f2tf32(v.z * ATTN_SCALE); u.w = f2tf32(v.w * ATTN_SCALE);
        *(uint4*)(bufK + row * PITCH + c4) = u;
    }
    __syncthreads();

    uint32_t qa[32];
#pragma unroll
    for (int ks = 0; ks < 8; ks++) {
        const uint32_t* qlo = bufK + (wid * 16 + qp) * PITCH + ks * 8 + c;
        const uint32_t* qhi = qlo + 8 * PITCH;
        qa[ks*4+0] = qlo[0];
        qa[ks*4+1] = qhi[0];
        qa[ks*4+2] = qlo[4];
        qa[ks*4+3] = qhi[4];
    }
    __syncthreads();

    float oc[8][4];
#pragma unroll
    for (int t = 0; t < 8; t++)
#pragma unroll
        for (int r = 0; r < 4; r++) oc[t][r] = 0.f;
    float m_lo = -1e30f, m_hi = -1e30f;
    float l_lo = 0.f,    l_hi = 0.f;

    for (int kt = 0; kt < SEQ / 128; kt++) {
#pragma unroll
        for (int i = 0; i < 8; i++) {
            int idx = tid + i * 256;
            int row = idx >> 4, c4 = (idx & 15) * 4;
            float4 v = *(const float4*)(kbase + ((size_t)kt * 128 + row) * HEAD_DIM + c4);
            uint4 u;
            u.x = f2tf32(v.x); u.y = f2tf32(v.y); u.z = f2tf32(v.z); u.w = f2tf32(v.w);
            *(uint4*)(bufK + row * PITCH + c4) = u;
        }
#pragma unroll
        for (int i = 0; i < 8; i++) {
            int idx = tid + i * 256;
            int row = idx >> 4, c4 = (idx & 15) * 4;
            float4 v = *(const float4*)(vbase + ((size_t)kt * 128 + row) * HEAD_DIM + c4);
            uint4 u;
            u.x = f2tf32(v.x); u.y = f2tf32(v.y); u.z = f2tf32(v.z); u.w = f2tf32(v.w);
            *(uint4*)(bufV + row * PITCH + c4) = u;
        }
        __syncthreads();

        float sc[16][4];
#pragma unroll
        for (int t = 0; t < 16; t++)
#pragma unroll
            for (int r = 0; r < 4; r++) sc[t][r] = 0.f;

#pragma unroll
        for (int nt = 0; nt < 16; nt++) {
            const uint32_t* kr = bufK + (nt * 8 + qp) * PITCH + c;
#pragma unroll
            for (int ks = 0; ks < 8; ks++) {
                uint32_t b0 = kr[ks * 8];
                uint32_t b1 = kr[ks * 8 + 4];
                mma_tf32(sc[nt], qa + ks * 4, b0, b1);
            }
        }

        float mx_lo = -1e30f, mx_hi = -1e30f;
#pragma unroll
        for (int t = 0; t < 16; t++) {
            mx_lo = fmaxf(mx_lo, fmaxf(sc[t][0], sc[t][1]));
            mx_hi = fmaxf(mx_hi, fmaxf(sc[t][2], sc[t][3]));
        }
        mx_lo = fmaxf(mx_lo, __shfl_xor_sync(0xffffffffu, mx_lo, 1));
        mx_lo = fmaxf(mx_lo, __shfl_xor_sync(0xffffffffu, mx_lo, 2));
        mx_hi = fmaxf(mx_hi, __shfl_xor_sync(0xffffffffu, mx_hi, 1));
        mx_hi = fmaxf(mx_hi, __shfl_xor_sync(0xffffffffu, mx_hi, 2));

        float mn_lo = fmaxf(m_lo, mx_lo);
        float mn_hi = fmaxf(m_hi, mx_hi);
        float al_lo = __expf(m_lo - mn_lo);
        float al_hi = __expf(m_hi - mn_hi);
        m_lo = mn_lo; m_hi = mn_hi;

        float s_lo = 0.f, s_hi = 0.f;
#pragma unroll
        for (int t = 0; t < 16; t++) {
            sc[t][0] = __expf(sc[t][0] - mn_lo);
            sc[t][1] = __expf(sc[t][1] - mn_lo);
            sc[t][2] = __expf(sc[t][2] - mn_hi);
            sc[t][3] = __expf(sc[t][3] - mn_hi);
            s_lo += sc[t][0] + sc[t][1];
            s_hi += sc[t][2] + sc[t][3];
        }
        l_lo = al_lo * l_lo + s_lo;
        l_hi = al_hi * l_hi + s_hi;

#pragma unroll
        for (int t = 0; t < 8; t++) {
            oc[t][0] *= al_lo; oc[t][1] *= al_lo;
            oc[t][2] *= al_hi; oc[t][3] *= al_hi;
        }

#pragma unroll
        for (int ks = 0; ks < 16; ks++) {
            int s0 = c >> 1;
            int s1 = 2 + (c >> 1);
            float t0 = __shfl_sync(0xffffffffu, sc[ks][0], s0, 4);
            float t1 = __shfl_sync(0xffffffffu, sc[ks][1], s0, 4);
            float t2 = __shfl_sync(0xffffffffu, sc[ks][2], s0, 4);
            float t3 = __shfl_sync(0xffffffffu, sc[ks][3], s0, 4);
            float u0 = __shfl_sync(0xffffffffu, sc[ks][0], s1, 4);
            float u1 = __shfl_sync(0xffffffffu, sc[ks][1], s1, 4);
            float u2 = __shfl_sync(0xffffffffu, sc[ks][2], s1, 4);
            float u3 = __shfl_sync(0xffffffffu, sc[ks][3], s1, 4);
            uint32_t a[4];
            a[0] = __float_as_uint((c & 1) ? t1 : t0);
            a[1] = __float_as_uint((c & 1) ? t3 : t2);
            a[2] = __float_as_uint((c & 1) ? u1 : u0);
            a[3] = __float_as_uint((c & 1) ? u3 : u2);

            const uint32_t* vr = bufV + (ks * 8 + c) * PITCH + qp;
#pragma unroll
            for (int nt = 0; nt < 8; nt++) {
                uint32_t b0 = vr[nt * 8];
                uint32_t b1 = vr[4 * PITCH + nt * 8];
                mma_tf32(oc[nt], a, b0, b1);
            }
        }
        __syncthreads();
    }

    l_lo += __shfl_xor_sync(0xffffffffu, l_lo, 1);
    l_lo += __shfl_xor_sync(0xffffffffu, l_lo, 2);
    l_hi += __shfl_xor_sync(0xffffffffu, l_hi, 1);
    l_hi += __shfl_xor_sync(0xffffffffu, l_hi, 2);
    const float inv_lo = 1.f / l_lo;
    const float inv_hi = 1.f / l_hi;

    const int b = bh >> 3, h = bh & 7;
    const int n_lo = qt * 128 + wid * 16 + qp;
    const int n_hi = n_lo + 8;
    float* olo = g_attn + (((size_t)b * SEQ + n_lo) * HEADS + h) * HEAD_DIM;
    float* ohi = g_attn + (((size_t)b * SEQ + n_hi) * HEADS + h) * HEAD_DIM;
#pragma unroll
    for (int t = 0; t < 8; t++) {
        int d = t * 8 + c * 2;
        *(float2*)(olo + d) = make_float2(oc[t][0] * inv_lo, oc[t][1] * inv_lo);
        *(float2*)(ohi + d) = make_float2(oc[t][2] * inv_hi, oc[t][3] * inv_hi);
    }
}

// ---------------------------------------------------------------------------

extern "C" void kernel_launch(void* const* d_in, const int* in_sizes, int n_in,
                              void* d_out, int out_size) {
    const float* x      = (const float*)d_in[0];
    const float* qkv_w  = (const float*)d_in[1];
    const float* qkv_b  = (const float*)d_in[2];
    const float* proj_w = (const float*)d_in[3];
    const float* proj_b = (const float*)d_in[4];
    float* out = (float*)d_out;

    cudaFuncSetAttribute(flash_attn_mma,
                         cudaFuncAttributeMaxDynamicSharedMemorySize, FLASH_DYN);

    qkv_gemm_tc<<<dim3(12, 64), 256>>>(x, qkv_w, qkv_b);
    flash_attn_mma<<<16 * (SEQ / 128), 256, FLASH_DYN>>>();
    proj_gemm_tc<<<dim3(4, 64), 256>>>(proj_w, proj_b, out);
}

// round 7
// speedup vs baseline: 5.0325x; 1.0629x over previous
#include <cuda_runtime.h>
#include <cstdint>

#define DIM 512
#define HEADS 8
#define HEAD_DIM 64
#define BATCH 2
#define SEQ 4096
#define M_TOT (BATCH*SEQ)           // 8192
#define ATTN_SCALE 0.125f           // 64^-0.5

// Scratch (allocation-free: device globals)
__device__ float g_q[BATCH*HEADS*SEQ*HEAD_DIM];
__device__ float g_k[BATCH*HEADS*SEQ*HEAD_DIM];
__device__ float g_v[BATCH*HEADS*SEQ*HEAD_DIM];
__device__ float g_attn[M_TOT*DIM];

// ---------------------------------------------------------------------------
// mma.sync m16n8k8 tf32 (baseline PTX) + helpers
// ---------------------------------------------------------------------------
__device__ __forceinline__ void mma_tf32(float* d, const uint32_t* a,
                                         uint32_t b0, uint32_t b1) {
    asm volatile(
        "mma.sync.aligned.m16n8k8.row.col.f32.tf32.tf32.f32 "
        "{%0,%1,%2,%3}, {%4,%5,%6,%7}, {%8,%9}, {%0,%1,%2,%3};"
        : "+f"(d[0]), "+f"(d[1]), "+f"(d[2]), "+f"(d[3])
        : "r"(a[0]), "r"(a[1]), "r"(a[2]), "r"(a[3]), "r"(b0), "r"(b1));
}

__device__ __forceinline__ uint32_t f2tf32(float x) {
    uint32_t r;
    asm("cvt.rna.tf32.f32 %0, %1;" : "=r"(r) : "f"(x));
    return r;
}

__device__ __forceinline__ uint32_t smem_u32(const void* p) {
    uint32_t a;
    asm("{ .reg .u64 t; cvta.to.shared.u64 t, %1; cvt.u32.u64 %0, t; }"
        : "=r"(a) : "l"(p));
    return a;
}

#define CP_ASYNC16(dst, src) \
    asm volatile("cp.async.cg.shared.global [%0], [%1], 16;" \
                 :: "r"(dst), "l"(src) : "memory")
#define CP_COMMIT() asm volatile("cp.async.commit_group;" ::: "memory")
#define CP_WAIT0()  asm volatile("cp.async.wait_group 0;" ::: "memory")

// ===========================================================================
// Split-precision tf32 tensor GEMM, hi/lo computed at STAGING time.
// CTA 128x128, BK=16, 256 threads (8 warps 2m x 4n, warp tile 64x32).
// Dynamic smem: Ah/Al/Wh/Wl, 2 stages each.  Mainloop: LDS + HMMA only.
// ===========================================================================
#define GP 20
#define GST (128 * GP)                 // 2560 u32 per stage-buffer
#define GEMM_SMEM (8 * GST * 4)        // 81,920 B

#define SPLIT_STORE(BH, BL, off, v) do {                                     \
    uint4 _h, _l;                                                            \
    _h.x = f2tf32((v).x); _l.x = f2tf32((v).x - __uint_as_float(_h.x));      \
    _h.y = f2tf32((v).y); _l.y = f2tf32((v).y - __uint_as_float(_h.y));      \
    _h.z = f2tf32((v).z); _l.z = f2tf32((v).z - __uint_as_float(_h.z));      \
    _h.w = f2tf32((v).w); _l.w = f2tf32((v).w - __uint_as_float(_h.w));      \
    *(uint4*)((BH) + (off)) = _h;                                            \
    *(uint4*)((BL) + (off)) = _l;                                            \
} while (0)

#define GEMM_BODY(Aptr, Wptr)                                                \
    extern __shared__ uint32_t gsm[];                                        \
    uint32_t* Ah = gsm;                                                      \
    uint32_t* Al = gsm + 2 * GST;                                            \
    uint32_t* Wh = gsm + 4 * GST;                                            \
    uint32_t* Wl = gsm + 6 * GST;                                            \
    const int tid  = threadIdx.x;                                            \
    const int m0   = blockIdx.y * 128;                                       \
    const int n0   = blockIdx.x * 128;                                       \
    const int wid  = tid >> 5, lane = tid & 31;                              \
    const int qp   = lane >> 2, c = lane & 3;                                \
    const int wm   = (wid >> 2) * 64;                                        \
    const int wn   = (wid & 3) * 32;                                         \
    float C[16][4];                                                          \
    _Pragma("unroll")                                                        \
    for (int t = 0; t < 16; t++)                                             \
        { C[t][0] = 0.f; C[t][1] = 0.f; C[t][2] = 0.f; C[t][3] = 0.f; }      \
    const int srow0 = tid >> 2, sc4 = (tid & 3) * 4;                         \
    const int srow1 = srow0 + 64;                                            \
    {                                                                        \
        float4 a0 = *(const float4*)(Aptr + (size_t)(m0 + srow0) * DIM + sc4); \
        float4 a1 = *(const float4*)(Aptr + (size_t)(m0 + srow1) * DIM + sc4); \
        float4 w0 = *(const float4*)(Wptr + (size_t)(n0 + srow0) * DIM + sc4); \
        float4 w1 = *(const float4*)(Wptr + (size_t)(n0 + srow1) * DIM + sc4); \
        SPLIT_STORE(Ah, Al, srow0 * GP + sc4, a0);                           \
        SPLIT_STORE(Ah, Al, srow1 * GP + sc4, a1);                           \
        SPLIT_STORE(Wh, Wl, srow0 * GP + sc4, w0);                           \
        SPLIT_STORE(Wh, Wl, srow1 * GP + sc4, w1);                           \
    }                                                                        \
    __syncthreads();                                                         \
    for (int s = 0; s < DIM / 16; s++) {                                     \
        const int cur = (s & 1) * GST;                                       \
        float4 pa0, pa1, pw0, pw1;                                           \
        if (s < DIM / 16 - 1) {                                              \
            int nk = (s + 1) * 16;                                           \
            pa0 = *(const float4*)(Aptr + (size_t)(m0 + srow0) * DIM + nk + sc4); \
            pa1 = *(const float4*)(Aptr + (size_t)(m0 + srow1) * DIM + nk + sc4); \
            pw0 = *(const float4*)(Wptr + (size_t)(n0 + srow0) * DIM + nk + sc4); \
            pw1 = *(const float4*)(Wptr + (size_t)(n0 + srow1) * DIM + nk + sc4); \
        }                                                                    \
        _Pragma("unroll")                                                    \
        for (int kk = 0; kk < 2; kk++) {                                     \
            uint32_t ahi[16], alo[16], bhi[8], blo[8];                       \
            _Pragma("unroll")                                                \
            for (int mt = 0; mt < 4; mt++) {                                 \
                int off = cur + (wm + mt * 16 + qp) * GP + kk * 8 + c;       \
                ahi[mt*4+0] = Ah[off];                                       \
                ahi[mt*4+1] = Ah[off + 8 * GP];                              \
                ahi[mt*4+2] = Ah[off + 4];                                   \
                ahi[mt*4+3] = Ah[off + 8 * GP + 4];                          \
                alo[mt*4+0] = Al[off];                                       \
                alo[mt*4+1] = Al[off + 8 * GP];                              \
                alo[mt*4+2] = Al[off + 4];                                   \
                alo[mt*4+3] = Al[off + 8 * GP + 4];                          \
            }                                                                \
            _Pragma("unroll")                                                \
            for (int nt = 0; nt < 4; nt++) {                                 \
                int off = cur + (wn + nt * 8 + qp) * GP + kk * 8 + c;        \
                bhi[nt*2+0] = Wh[off];                                       \
                bhi[nt*2+1] = Wh[off + 4];                                   \
                blo[nt*2+0] = Wl[off];                                       \
                blo[nt*2+1] = Wl[off + 4];                                   \
            }                                                                \
            _Pragma("unroll")                                                \
            for (int mt = 0; mt < 4; mt++)                                   \
                _Pragma("unroll")                                            \
                for (int nt = 0; nt < 4; nt++) {                             \
                    mma_tf32(C[mt*4+nt], ahi + mt*4, bhi[nt*2], bhi[nt*2+1]); \
                    mma_tf32(C[mt*4+nt], ahi + mt*4, blo[nt*2], blo[nt*2+1]); \
                    mma_tf32(C[mt*4+nt], alo + mt*4, bhi[nt*2], bhi[nt*2+1]); \
                }                                                            \
        }                                                                    \
        if (s < DIM / 16 - 1) {                                              \
            const int nb = ((s + 1) & 1) * GST;                              \
            SPLIT_STORE(Ah + nb, Al + nb, srow0 * GP + sc4, pa0);            \
            SPLIT_STORE(Ah + nb, Al + nb, srow1 * GP + sc4, pa1);            \
            SPLIT_STORE(Wh + nb, Wl + nb, srow0 * GP + sc4, pw0);            \
            SPLIT_STORE(Wh + nb, Wl + nb, srow1 * GP + sc4, pw1);            \
        }                                                                    \
        __syncthreads();                                                     \
    }

__global__ __launch_bounds__(256) void qkv_gemm_tc(const float* __restrict__ A,
                                                   const float* __restrict__ W,
                                                   const float* __restrict__ bias) {
    GEMM_BODY(A, W)
#pragma unroll
    for (int mt = 0; mt < 4; mt++) {
#pragma unroll
        for (int nt = 0; nt < 4; nt++) {
#pragma unroll
            for (int half = 0; half < 2; half++) {
                int m  = m0 + wm + mt * 16 + qp + half * 8;
                int b  = m >> 12;
                int nn = m & 4095;
                int n  = n0 + wn + nt * 8 + c * 2;
                float v0 = C[mt*4+nt][half*2+0] + bias[n];
                float v1 = C[mt*4+nt][half*2+1] + bias[n + 1];
                int which = n >> 9;
                int cc = n & 511;
                int h  = cc >> 6;
                int d  = cc & 63;
                int bhh = b * HEADS + h;
                float* dst = (which == 0) ? g_q : ((which == 1) ? g_k : g_v);
                *(float2*)(dst + ((size_t)bhh * SEQ + nn) * HEAD_DIM + d) =
                    make_float2(v0, v1);
            }
        }
    }
}

__global__ __launch_bounds__(256) void proj_gemm_tc(const float* __restrict__ W,
                                                    const float* __restrict__ bias,
                                                    float* __restrict__ out) {
    const float* Ain = g_attn;
    GEMM_BODY(Ain, W)
#pragma unroll
    for (int mt = 0; mt < 4; mt++) {
#pragma unroll
        for (int nt = 0; nt < 4; nt++) {
#pragma unroll
            for (int half = 0; half < 2; half++) {
                int m = m0 + wm + mt * 16 + qp + half * 8;
                int n = n0 + wn + nt * 8 + c * 2;
                float v0 = C[mt*4+nt][half*2+0] + bias[n];
                float v1 = C[mt*4+nt][half*2+1] + bias[n + 1];
                *(float2*)(out + (size_t)m * DIM + n) = make_float2(v0, v1);
            }
        }
    }
}

// ===========================================================================
// Flash attention: 64-row CTAs (4 warps), 3 CTAs/SM, cp.async K/V staging.
// K/V consumed as raw fp32 bits by mma.tf32 (rz truncation); Q rna-rounded.
// ===========================================================================
#define FPITCH 68
#define FTILE (128 * FPITCH)               // u32 per tile
#define FLASH_SMEM (2 * FTILE * 4)         // 69,632 B

__global__ __launch_bounds__(128, 3) void flash_attn_mma() {
    extern __shared__ uint32_t sbuf[];
    uint32_t* bufK = sbuf;
    uint32_t* bufV = sbuf + FTILE;
    const uint32_t skb = smem_u32(bufK);
    const uint32_t svb = smem_u32(bufV);

    const int tid  = threadIdx.x;
    const int wid  = tid >> 5;             // 0..3
    const int lane = tid & 31;
    const int qp   = lane >> 2;
    const int c    = lane & 3;

    const int bh = blockIdx.x >> 6;        // 0..15
    const int qt = blockIdx.x & 63;        // 64-row query tile

    const float* qbase = g_q + ((size_t)bh * SEQ + (size_t)qt * 64) * HEAD_DIM;
    const float* kbase = g_k + (size_t)bh * SEQ * HEAD_DIM;
    const float* vbase = g_v + (size_t)bh * SEQ * HEAD_DIM;

    // Stage Q (scaled, rna) into bufK temporarily, extract A-fragments.
#pragma unroll
    for (int i = 0; i < 8; i++) {
        int idx = tid + i * 128;           // 0..1023
        int row = idx >> 4, c4 = (idx & 15) * 4;
        float4 v = *(const float4*)(qbase + (size_t)row * HEAD_DIM + c4);
        uint4 u;
        u.x = f2tf32(v.x * ATTN_SCALE); u.y = f2tf32(v.y * ATTN_SCALE);
        u.z = f2tf32(v.z * ATTN_SCALE); u.w = f2tf32(v.w * ATTN_SCALE);
        *(uint4*)(bufK + row * FPITCH + c4) = u;
    }
    __syncthreads();

    uint32_t qa[32];
#pragma unroll
    for (int ks = 0; ks < 8; ks++) {
        const uint32_t* qlo = bufK + (wid * 16 + qp) * FPITCH + ks * 8 + c;
        const uint32_t* qhi = qlo + 8 * FPITCH;
        qa[ks*4+0] = qlo[0];
        qa[ks*4+1] = qhi[0];
        qa[ks*4+2] = qlo[4];
        qa[ks*4+3] = qhi[4];
    }
    __syncthreads();

    float oc[8][4];
#pragma unroll
    for (int t = 0; t < 8; t++)
#pragma unroll
        for (int r = 0; r < 4; r++) oc[t][r] = 0.f;
    float m_lo = -1e30f, m_hi = -1e30f;
    float l_lo = 0.f,    l_hi = 0.f;

    for (int kt = 0; kt < SEQ / 128; kt++) {
        // ---- Stage K, V via cp.async (raw fp32) ----
#pragma unroll
        for (int i = 0; i < 16; i++) {
            int idx = tid + i * 128;       // 0..2047 chunks of 16B
            int row = idx >> 4, c4 = (idx & 15) * 4;
            uint32_t soff = (uint32_t)(row * FPITCH + c4) * 4u;
            const float* gk = kbase + ((size_t)kt * 128 + row) * HEAD_DIM + c4;
            const float* gv = vbase + ((size_t)kt * 128 + row) * HEAD_DIM + c4;
            CP_ASYNC16(skb + soff, gk);
            CP_ASYNC16(svb + soff, gv);
        }
        CP_COMMIT();
        CP_WAIT0();
        __syncthreads();

        // ---- S = Q @ K^T ----
        float sc[16][4];
#pragma unroll
        for (int t = 0; t < 16; t++)
#pragma unroll
            for (int r = 0; r < 4; r++) sc[t][r] = 0.f;

#pragma unroll
        for (int nt = 0; nt < 16; nt++) {
            const uint32_t* kr = bufK + (nt * 8 + qp) * FPITCH + c;
#pragma unroll
            for (int ks = 0; ks < 8; ks++) {
                uint32_t b0 = kr[ks * 8];
                uint32_t b1 = kr[ks * 8 + 4];
                mma_tf32(sc[nt], qa + ks * 4, b0, b1);
            }
        }

        // ---- Online softmax (quad-level reductions) ----
        float mx_lo = -1e30f, mx_hi = -1e30f;
#pragma unroll
        for (int t = 0; t < 16; t++) {
            mx_lo = fmaxf(mx_lo, fmaxf(sc[t][0], sc[t][1]));
            mx_hi = fmaxf(mx_hi, fmaxf(sc[t][2], sc[t][3]));
        }
        mx_lo = fmaxf(mx_lo, __shfl_xor_sync(0xffffffffu, mx_lo, 1));
        mx_lo = fmaxf(mx_lo, __shfl_xor_sync(0xffffffffu, mx_lo, 2));
        mx_hi = fmaxf(mx_hi, __shfl_xor_sync(0xffffffffu, mx_hi, 1));
        mx_hi = fmaxf(mx_hi, __shfl_xor_sync(0xffffffffu, mx_hi, 2));

        float mn_lo = fmaxf(m_lo, mx_lo);
        float mn_hi = fmaxf(m_hi, mx_hi);
        float al_lo = __expf(m_lo - mn_lo);
        float al_hi = __expf(m_hi - mn_hi);
        m_lo = mn_lo; m_hi = mn_hi;

        float s_lo = 0.f, s_hi = 0.f;
#pragma unroll
        for (int t = 0; t < 16; t++) {
            sc[t][0] = __expf(sc[t][0] - mn_lo);
            sc[t][1] = __expf(sc[t][1] - mn_lo);
            sc[t][2] = __expf(sc[t][2] - mn_hi);
            sc[t][3] = __expf(sc[t][3] - mn_hi);
            s_lo += sc[t][0] + sc[t][1];
            s_hi += sc[t][2] + sc[t][3];
        }
        l_lo = al_lo * l_lo + s_lo;
        l_hi = al_hi * l_hi + s_hi;

#pragma unroll
        for (int t = 0; t < 8; t++) {
            oc[t][0] *= al_lo; oc[t][1] *= al_lo;
            oc[t][2] *= al_hi; oc[t][3] *= al_hi;
        }

        // ---- O += P @ V ----
#pragma unroll
        for (int ks = 0; ks < 16; ks++) {
            int s0 = c >> 1;
            int s1 = 2 + (c >> 1);
            float t0 = __shfl_sync(0xffffffffu, sc[ks][0], s0, 4);
            float t1 = __shfl_sync(0xffffffffu, sc[ks][1], s0, 4);
            float t2 = __shfl_sync(0xffffffffu, sc[ks][2], s0, 4);
            float t3 = __shfl_sync(0xffffffffu, sc[ks][3], s0, 4);
            float u0 = __shfl_sync(0xffffffffu, sc[ks][0], s1, 4);
            float u1 = __shfl_sync(0xffffffffu, sc[ks][1], s1, 4);
            float u2 = __shfl_sync(0xffffffffu, sc[ks][2], s1, 4);
            float u3 = __shfl_sync(0xffffffffu, sc[ks][3], s1, 4);
            uint32_t a[4];
            a[0] = __float_as_uint((c & 1) ? t1 : t0);
            a[1] = __float_as_uint((c & 1) ? t3 : t2);
            a[2] = __float_as_uint((c & 1) ? u1 : u0);
            a[3] = __float_as_uint((c & 1) ? u3 : u2);

            const uint32_t* vr = bufV + (ks * 8 + c) * FPITCH + qp;
#pragma unroll
            for (int nt = 0; nt < 8; nt++) {
                uint32_t b0 = vr[nt * 8];
                uint32_t b1 = vr[4 * FPITCH + nt * 8];
                mma_tf32(oc[nt], a, b0, b1);
            }
        }
        __syncthreads();
    }

    // ---- Final: reduce l across quad, normalize, write ----
    l_lo += __shfl_xor_sync(0xffffffffu, l_lo, 1);
    l_lo += __shfl_xor_sync(0xffffffffu, l_lo, 2);
    l_hi += __shfl_xor_sync(0xffffffffu, l_hi, 1);
    l_hi += __shfl_xor_sync(0xffffffffu, l_hi, 2);
    const float inv_lo = 1.f / l_lo;
    const float inv_hi = 1.f / l_hi;

    const int b = bh >> 3, h = bh & 7;
    const int n_lo = qt * 64 + wid * 16 + qp;
    const int n_hi = n_lo + 8;
    float* olo = g_attn + (((size_t)b * SEQ + n_lo) * HEADS + h) * HEAD_DIM;
    float* ohi = g_attn + (((size_t)b * SEQ + n_hi) * HEADS + h) * HEAD_DIM;
#pragma unroll
    for (int t = 0; t < 8; t++) {
        int d = t * 8 + c * 2;
        *(float2*)(olo + d) = make_float2(oc[t][0] * inv_lo, oc[t][1] * inv_lo);
        *(float2*)(ohi + d) = make_float2(oc[t][2] * inv_hi, oc[t][3] * inv_hi);
    }
}

// ---------------------------------------------------------------------------

extern "C" void kernel_launch(void* const* d_in, const int* in_sizes, int n_in,
                              void* d_out, int out_size) {
    const float* x      = (const float*)d_in[0];
    const float* qkv_w  = (const float*)d_in[1];
    const float* qkv_b  = (const float*)d_in[2];
    const float* proj_w = (const float*)d_in[3];
    const float* proj_b = (const float*)d_in[4];
    float* out = (float*)d_out;

    cudaFuncSetAttribute(qkv_gemm_tc,
                         cudaFuncAttributeMaxDynamicSharedMemorySize, GEMM_SMEM);
    cudaFuncSetAttribute(proj_gemm_tc,
                         cudaFuncAttributeMaxDynamicSharedMemorySize, GEMM_SMEM);
    cudaFuncSetAttribute(flash_attn_mma,
                         cudaFuncAttributeMaxDynamicSharedMemorySize, FLASH_SMEM);

    qkv_gemm_tc<<<dim3(12, 64), 256, GEMM_SMEM>>>(x, qkv_w, qkv_b);
    flash_attn_mma<<<16 * (SEQ / 64), 128, FLASH_SMEM>>>();
    proj_gemm_tc<<<dim3(4, 64), 256, GEMM_SMEM>>>(proj_w, proj_b, out);
}